// round 7
// baseline (speedup 1.0000x reference)
#include <cuda_runtime.h>
#include <cstdint>

#define NB     32
#define NS     1024
#define ROWS   (NB * NS)     // 32768
#define KNN    32
#define NIN    64            // 2*K
#define MID    32
#define TPB    128           // threads per block (32 rows/block)
#define WSTRIDE 516          // floats between lane-group weight bases (512 + 4 pad)

// packed f32x2 ops (sm_100+)
__device__ __forceinline__ unsigned long long fma2(unsigned long long a,
                                                   unsigned long long b,
                                                   unsigned long long c) {
    unsigned long long d;
    asm("fma.rn.f32x2 %0, %1, %2, %3;" : "=l"(d) : "l"(a), "l"(b), "l"(c));
    return d;
}
__device__ __forceinline__ unsigned long long add2(unsigned long long a,
                                                   unsigned long long b) {
    unsigned long long d;
    asm("add.rn.f32x2 %0, %1, %2;" : "=l"(d) : "l"(a), "l"(b));
    return d;
}
__device__ __forceinline__ unsigned long long pack2(float lo, float hi) {
    unsigned long long d;
    asm("mov.b64 %0, {%1, %2};" : "=l"(d) : "f"(lo), "f"(hi));
    return d;
}
__device__ __forceinline__ void unpack2(unsigned long long v, float& lo, float& hi) {
    asm("mov.b64 {%0, %1}, %2;" : "=f"(lo), "=f"(hi) : "l"(v));
}

// tanh(x) = 1 - 2/(exp(2x)+1) via ex2.approx + rcp.approx (~1e-6 rel err)
__device__ __forceinline__ float fast_tanh(float x) {
    float e, r;
    asm("ex2.approx.f32 %0, %1;" : "=f"(e) : "f"(x * 2.8853900817779268f));
    asm("rcp.approx.f32 %0, %1;" : "=f"(r) : "f"(e + 1.0f));
    return fmaf(-2.0f, r, 1.0f);
}

__global__ __launch_bounds__(TPB, 1)
void metak_kernel(const int*   __restrict__ vals,
                  const float* __restrict__ dist,
                  const float* __restrict__ fc2_w1,   // [64,32]
                  const float* __restrict__ fc2_b1,   // [32]
                  const float* __restrict__ fc2_w2,   // [32,2]
                  const float* __restrict__ fc2_b2,   // [2]
                  const float* __restrict__ fc1_w1,   // [2,4]
                  const float* __restrict__ fc1_b1,   // [4]
                  const float* __restrict__ fc1_w2,   // [4,1]
                  const float* __restrict__ fc1_b2,   // [1]
                  float*       __restrict__ out)
{
    // weight row k lives at k*32 + (k>>4)*4 : +16B pad per 16-row group so the
    // four lane-groups' broadcast LDS.128 hit disjoint bank quads.
    __shared__ __align__(16) float sw1[4 * WSTRIDE];   // 2064 floats
    __shared__ __align__(16) float sb1[MID];
    __shared__ __align__(16) float sw2[MID * 2];
    __shared__ float sb2[2];
    __shared__ float sf1w1[8];
    __shared__ float sf1b1[4];
    __shared__ float sf1w2[4];
    __shared__ float sf1b2;

    const int tid = threadIdx.x;
    for (int i = tid; i < NIN * MID; i += TPB) {
        int k = i >> 5;
        sw1[i + (k >> 4) * 4] = fc2_w1[i];
    }
    if (tid < MID)     sb1[tid]   = fc2_b1[tid];
    if (tid < MID * 2) sw2[tid]   = fc2_w2[tid];
    if (tid < 2)       sb2[tid]   = fc2_b2[tid];
    if (tid < 8)       sf1w1[tid] = fc1_w1[tid];
    if (tid < 4)       sf1b1[tid] = fc1_b1[tid];
    if (tid < 4)       sf1w2[tid] = fc1_w2[tid];
    if (tid == 0)      sf1b2      = fc1_b2[0];
    __syncthreads();

    const int gt  = blockIdx.x * TPB + tid;   // 4 threads per row
    const int row = gt >> 2;
    const int q   = gt & 3;                   // k-quarter: 0,1=dist  2,3=counts

    // ---- every lane: scan its row's labels -> prefix distinct-nonzero counts ----
    const int4* vp = reinterpret_cast<const int4*>(vals) + (size_t)row * 8;
    int4 v[8];
#pragma unroll
    for (int i = 0; i < 8; i++) v[i] = vp[i];

    float c[KNN];
    {
        unsigned long long m0 = 1ull, m1 = 0ull;   // bit0 set: label 0 never counts
        int cnt = 0;
#pragma unroll
        for (int i = 0; i < 8; i++) {
#pragma unroll
            for (int e = 0; e < 4; e++) {
                int vv = (e == 0) ? v[i].x : (e == 1) ? v[i].y
                       : (e == 2) ? v[i].z : v[i].w;
                unsigned long long bit = 1ull << (vv & 63);
                bool hi = (vv & 64) != 0;
                unsigned long long cur = hi ? m1 : m0;
                cnt += (int)((cur & bit) == 0ull);
                cur |= bit;
                if (hi) m1 = cur; else m0 = cur;
                c[4 * i + e] = (float)cnt;
            }
        }
    }

    // ---- select this lane's 16 inputs ----
    float x[16];
#pragma unroll
    for (int t = 0; t < 16; t++)
        x[t] = (q & 1) ? c[16 + t] : c[t];      // valid for q=2,3; q<2 overwritten

    {
        const float4* dp = reinterpret_cast<const float4*>(dist) + (size_t)row * 8;
        float4 dd[8];
#pragma unroll
        for (int i = 0; i < 8; i++) dd[i] = dp[i];
#pragma unroll
        for (int t = 0; t < 16; t++) {
            float dlo = (t % 4 == 0) ? dd[t / 4].x : (t % 4 == 1) ? dd[t / 4].y
                      : (t % 4 == 2) ? dd[t / 4].z : dd[t / 4].w;
            int t2 = 16 + t;
            float dhi = (t2 % 4 == 0) ? dd[t2 / 4].x : (t2 % 4 == 1) ? dd[t2 / 4].y
                      : (t2 % 4 == 2) ? dd[t2 / 4].z : dd[t2 / 4].w;
            x[t] = (q == 0) ? dlo : (q == 1) ? dhi : x[t];
        }
    }

    // ---- quarter-GEMV: 16 k-values x 32 outputs (16 packed accumulators) ----
    unsigned long long acc[16];
#pragma unroll
    for (int j = 0; j < 16; j++) acc[j] = 0ull;

    const float* wq = sw1 + q * WSTRIDE;
#pragma unroll
    for (int t = 0; t < 16; t++) {
        unsigned long long xp = pack2(x[t], x[t]);
        const ulonglong2* wrow = reinterpret_cast<const ulonglong2*>(wq + t * 32);
#pragma unroll
        for (int u = 0; u < 8; u++) {
            ulonglong2 w = wrow[u];
            acc[2 * u]     = fma2(xp, w.x, acc[2 * u]);
            acc[2 * u + 1] = fma2(xp, w.y, acc[2 * u + 1]);
        }
    }

    // ---- butterfly sum across the 4 lanes of this row ----
#pragma unroll
    for (int j = 0; j < 16; j++)
        acc[j] = add2(acc[j], __shfl_xor_sync(0xffffffffu, acc[j], 1));
#pragma unroll
    for (int j = 0; j < 16; j++)
        acc[j] = add2(acc[j], __shfl_xor_sync(0xffffffffu, acc[j], 2));

    // ---- + bias; each lane applies tanh+fc2b to its own 8 hidden units ----
    float o0 = 0.f, o1 = 0.f;
#pragma unroll
    for (int u = 0; u < 4; u++) {
        unsigned long long a = (q == 0) ? acc[u]     : (q == 1) ? acc[4 + u]
                             : (q == 2) ? acc[8 + u] : acc[12 + u];
        int h0 = 8 * q + 2 * u;                       // hidden-unit pair index
        float blo, bhi;
        const float2 bb = *reinterpret_cast<const float2*>(sb1 + h0);
        float av, bv;
        unpack2(a, av, bv);
        blo = bb.x; bhi = bb.y;
        float ha = fast_tanh(av + blo);
        float hb = fast_tanh(bv + bhi);
        float4 wv = *reinterpret_cast<const float4*>(sw2 + 2 * h0);
        o0 = fmaf(ha, wv.x, fmaf(hb, wv.z, o0));
        o1 = fmaf(ha, wv.y, fmaf(hb, wv.w, o1));
    }
    o0 += __shfl_xor_sync(0xffffffffu, o0, 1);
    o0 += __shfl_xor_sync(0xffffffffu, o0, 2);
    o1 += __shfl_xor_sync(0xffffffffu, o1, 1);
    o1 += __shfl_xor_sync(0xffffffffu, o1, 2);
    o0 += sb2[0];
    o1 += sb2[1];

    // ---- fc1 head (uniform across lanes), store from q==0 ----
    float r = sf1b2;
#pragma unroll
    for (int ci = 0; ci < 4; ci++) {
        float t = fast_tanh(fmaf(o1, sf1w1[4 + ci], fmaf(o0, sf1w1[ci], sf1b1[ci])));
        r = fmaf(t, sf1w2[ci], r);
    }

    if (q == 0) {
        float* op = out + (size_t)row * 3;
        op[0] = o0;
        op[1] = o1;
        op[2] = r;
    }
}

extern "C" void kernel_launch(void* const* d_in, const int* in_sizes, int n_in,
                              void* d_out, int out_size)
{
    const int*   vals   = (const int*)  d_in[0];
    const float* dist   = (const float*)d_in[1];
    const float* fc2_w1 = (const float*)d_in[2];
    const float* fc2_b1 = (const float*)d_in[3];
    const float* fc2_w2 = (const float*)d_in[4];
    const float* fc2_b2 = (const float*)d_in[5];
    const float* fc1_w1 = (const float*)d_in[6];
    const float* fc1_b1 = (const float*)d_in[7];
    const float* fc1_w2 = (const float*)d_in[8];
    const float* fc1_b2 = (const float*)d_in[9];
    float* out = (float*)d_out;

    const int blocks = (ROWS * 4) / TPB;   // 1024 blocks, 128 threads
    metak_kernel<<<blocks, TPB>>>(vals, dist,
                                  fc2_w1, fc2_b1, fc2_w2, fc2_b2,
                                  fc1_w1, fc1_b1, fc1_w2, fc1_b2,
                                  out);
}

// round 9
// speedup vs baseline: 1.7496x; 1.7496x over previous
#include <cuda_runtime.h>
#include <cstdint>

#define ROWS 32768
#define TPB  128
#define RPB  128            // rows per block == threads per block
#define XS   68             // padded row stride in smem (floats): 272B, 16B-aligned

__device__ __forceinline__ unsigned long long pack2(float lo, float hi) {
    unsigned long long d;
    asm("mov.b64 %0, {%1, %2};" : "=l"(d) : "f"(lo), "f"(hi));
    return d;
}
__device__ __forceinline__ void unpack2(unsigned long long v, float& lo, float& hi) {
    asm("mov.b64 {%0, %1}, %2;" : "=f"(lo), "=f"(hi) : "l"(v));
}
__device__ __forceinline__ unsigned long long add2(unsigned long long a,
                                                   unsigned long long b) {
    unsigned long long d;
    asm("add.rn.f32x2 %0, %1, %2;" : "=l"(d) : "l"(a), "l"(b));
    return d;
}

// tanh(x) = 1 - 2/(exp(2x)+1) via ex2.approx + rcp.approx (~1e-6 rel err)
__device__ __forceinline__ float fast_tanh(float x) {
    float e, r;
    asm("ex2.approx.f32 %0, %1;" : "=f"(e) : "f"(x * 2.8853900817779268f));
    asm("rcp.approx.f32 %0, %1;" : "=f"(r) : "f"(e + 1.0f));
    return fmaf(-2.0f, r, 1.0f);
}

__global__ __launch_bounds__(TPB)
void metak_kernel(const int*   __restrict__ vals,
                  const float* __restrict__ dist,
                  const float* __restrict__ fc2_w1,   // [64,32]
                  const float* __restrict__ fc2_b1,   // [32]
                  const float* __restrict__ fc2_w2,   // [32,2]
                  const float* __restrict__ fc2_b2,   // [2]
                  const float* __restrict__ fc1_w1,   // [2,4]
                  const float* __restrict__ fc1_b1,   // [4]
                  const float* __restrict__ fc1_w2,   // [4,1]
                  const float* __restrict__ fc1_b2,   // [1]
                  float*       __restrict__ out)
{
    __shared__ __align__(16) float xs[RPB * XS];    // 34816 B staged features

    const int tid  = threadIdx.x;
    const int lane = tid & 31;
    const int wid  = tid >> 5;
    const int rowblock = blockIdx.x * RPB;

    // ================= Phase 1: this thread scans ONE row =================
    {
        const int r = rowblock + tid;
        const float4* dp = reinterpret_cast<const float4*>(dist) + (size_t)r * 8;
        const int4*   vp = reinterpret_cast<const int4*>(vals) + (size_t)r * 8;

        float* xrow = xs + tid * XS;

        // distances: straight copy gmem -> smem (16 loads batched, MLP high)
        float4 d0 = dp[0], d1 = dp[1], d2 = dp[2], d3 = dp[3],
               d4 = dp[4], d5 = dp[5], d6 = dp[6], d7 = dp[7];
        int4   v0 = vp[0], v1 = vp[1], v2 = vp[2], v3 = vp[3],
               v4 = vp[4], v5 = vp[5], v6 = vp[6], v7 = vp[7];

        float4* xv = reinterpret_cast<float4*>(xrow);
        xv[0] = d0; xv[1] = d1; xv[2] = d2; xv[3] = d3;
        xv[4] = d4; xv[5] = d5; xv[6] = d6; xv[7] = d7;

        // prefix distinct-nonzero-label counts (labels in [0,100); bit0 preset)
        unsigned long long m0 = 1ull, m1 = 0ull;
        int cnt = 0;
        int4 vv4[8] = {v0, v1, v2, v3, v4, v5, v6, v7};
#pragma unroll
        for (int i = 0; i < 8; i++) {
            float t0, t1, t2, t3;
#pragma unroll
            for (int e = 0; e < 4; e++) {
                int vv = (e == 0) ? vv4[i].x : (e == 1) ? vv4[i].y
                       : (e == 2) ? vv4[i].z : vv4[i].w;
                unsigned long long bit = 1ull << (vv & 63);
                bool hi = (vv & 64) != 0;
                unsigned long long cur = hi ? m1 : m0;
                cnt += (int)((cur & bit) == 0ull);
                cur |= bit;
                if (hi) m1 = cur; else m0 = cur;
                float cf = (float)cnt;
                if (e == 0) t0 = cf; else if (e == 1) t1 = cf;
                else if (e == 2) t2 = cf; else t3 = cf;
            }
            xv[8 + i] = make_float4(t0, t1, t2, t3);
        }
    }

    // ====== load per-lane weights AFTER phase 1 (keeps reg peak low) ======
    float w[64];                                    // column `lane` of fc2_w1
#pragma unroll
    for (int k = 0; k < 64; k++) w[k] = fc2_w1[k * 32 + lane];
    const float  b1  = fc2_b1[lane];
    const float2 w2  = reinterpret_cast<const float2*>(fc2_w2)[lane];
    const float  b20 = fc2_b2[0], b21 = fc2_b2[1];
    float hw1[8], hb1v[4], hw2v[4];
#pragma unroll
    for (int i = 0; i < 8; i++) hw1[i] = fc1_w1[i];
#pragma unroll
    for (int i = 0; i < 4; i++) { hb1v[i] = fc1_b1[i]; hw2v[i] = fc1_w2[i]; }
    const float hb2 = fc1_b2[0];

    __syncwarp();   // warp consumes only rows its own lanes staged

    // ========= Phase 2: warp sweeps its 32 rows, 2 rows per iter =========
    const int wrow0 = wid * 32;                     // first row (in block) of warp
#pragma unroll 1
    for (int p = 0; p < 16; p++) {
        const float4* xa = reinterpret_cast<const float4*>(xs + (wrow0 + 2 * p)     * XS);
        const float4* xb = reinterpret_cast<const float4*>(xs + (wrow0 + 2 * p + 1) * XS);

        float acca = b1, accb = b1;
#pragma unroll
        for (int c = 0; c < 16; c++) {
            float4 a4 = xa[c];                       // uniform broadcast LDS.128
            float4 b4 = xb[c];
            acca = fmaf(a4.x, w[4*c + 0], acca);
            accb = fmaf(b4.x, w[4*c + 0], accb);
            acca = fmaf(a4.y, w[4*c + 1], acca);
            accb = fmaf(b4.y, w[4*c + 1], accb);
            acca = fmaf(a4.z, w[4*c + 2], acca);
            accb = fmaf(b4.z, w[4*c + 2], accb);
            acca = fmaf(a4.w, w[4*c + 3], acca);
            accb = fmaf(b4.w, w[4*c + 3], accb);
        }

        // lane j holds hidden unit j of both rows
        float ha = fast_tanh(acca);
        float hb = fast_tanh(accb);

        // partial (o0,o1) per lane, packed butterfly reduce over 32 lanes
        unsigned long long pa = pack2(ha * w2.x, ha * w2.y);
        unsigned long long pb = pack2(hb * w2.x, hb * w2.y);
#pragma unroll
        for (int off = 1; off < 32; off <<= 1) {
            pa = add2(pa, __shfl_xor_sync(0xffffffffu, pa, off));
            pb = add2(pb, __shfl_xor_sync(0xffffffffu, pb, off));
        }
        float o0a, o1a, o0b, o1b;
        unpack2(pa, o0a, o1a);
        unpack2(pb, o0b, o1b);
        o0a += b20; o1a += b21;
        o0b += b20; o1b += b21;

        // head (all lanes redundantly; cheap)
        float ra = hb2, rb = hb2;
#pragma unroll
        for (int c = 0; c < 4; c++) {
            float ta = fast_tanh(fmaf(o1a, hw1[4 + c], fmaf(o0a, hw1[c], hb1v[c])));
            float tb = fast_tanh(fmaf(o1b, hw1[4 + c], fmaf(o0b, hw1[c], hb1v[c])));
            ra = fmaf(ta, hw2v[c], ra);
            rb = fmaf(tb, hw2v[c], rb);
        }

        const int grow = rowblock + wrow0 + 2 * p;
        if (lane == 0) {
            float* op = out + (size_t)grow * 3;
            op[0] = o0a; op[1] = o1a; op[2] = ra;
        } else if (lane == 1) {
            float* op = out + (size_t)(grow + 1) * 3;
            op[0] = o0b; op[1] = o1b; op[2] = rb;
        }
    }
}

extern "C" void kernel_launch(void* const* d_in, const int* in_sizes, int n_in,
                              void* d_out, int out_size)
{
    const int*   vals   = (const int*)  d_in[0];
    const float* dist   = (const float*)d_in[1];
    const float* fc2_w1 = (const float*)d_in[2];
    const float* fc2_b1 = (const float*)d_in[3];
    const float* fc2_w2 = (const float*)d_in[4];
    const float* fc2_b2 = (const float*)d_in[5];
    const float* fc1_w1 = (const float*)d_in[6];
    const float* fc1_b1 = (const float*)d_in[7];
    const float* fc1_w2 = (const float*)d_in[8];
    const float* fc1_b2 = (const float*)d_in[9];
    float* out = (float*)d_out;

    const int blocks = ROWS / RPB;   // 256
    metak_kernel<<<blocks, TPB>>>(vals, dist,
                                  fc2_w1, fc2_b1, fc2_w2, fc2_b2,
                                  fc1_w1, fc1_b1, fc1_w2, fc1_b2,
                                  out);
}

// round 10
// speedup vs baseline: 2.2635x; 1.2937x over previous
#include <cuda_runtime.h>
#include <cstdint>

#define ROWS 32768
#define TPB  128
#define RPB  128            // rows per block == threads per block
#define XS   68             // padded row stride in smem (floats): 272B, 16B-aligned

__device__ __forceinline__ unsigned long long fma2(unsigned long long a,
                                                   unsigned long long b,
                                                   unsigned long long c) {
    unsigned long long d;
    asm("fma.rn.f32x2 %0, %1, %2, %3;" : "=l"(d) : "l"(a), "l"(b), "l"(c));
    return d;
}
__device__ __forceinline__ unsigned long long pack2(float lo, float hi) {
    unsigned long long d;
    asm("mov.b64 %0, {%1, %2};" : "=l"(d) : "f"(lo), "f"(hi));
    return d;
}
__device__ __forceinline__ void unpack2(unsigned long long v, float& lo, float& hi) {
    asm("mov.b64 {%0, %1}, %2;" : "=f"(lo), "=f"(hi) : "l"(v));
}

// tanh(x) = 1 - 2/(exp(2x)+1) via ex2.approx + rcp.approx (~1e-6 rel err)
__device__ __forceinline__ float fast_tanh(float x) {
    float e, r;
    asm("ex2.approx.f32 %0, %1;" : "=f"(e) : "f"(x * 2.8853900817779268f));
    asm("rcp.approx.f32 %0, %1;" : "=f"(r) : "f"(e + 1.0f));
    return fmaf(-2.0f, r, 1.0f);
}

__global__ __launch_bounds__(TPB)
void metak_kernel(const int*   __restrict__ vals,
                  const float* __restrict__ dist,
                  const float* __restrict__ fc2_w1,   // [64,32]
                  const float* __restrict__ fc2_b1,   // [32]
                  const float* __restrict__ fc2_w2,   // [32,2]
                  const float* __restrict__ fc2_b2,   // [2]
                  const float* __restrict__ fc1_w1,   // [2,4]
                  const float* __restrict__ fc1_b1,   // [4]
                  const float* __restrict__ fc1_w2,   // [4,1]
                  const float* __restrict__ fc1_b2,   // [1]
                  float*       __restrict__ out)
{
    // Staged features; after a row's GEMV, its h[32] overlays floats [0..31]
    // of the same row (the x data is dead by then). No separate hs array.
    __shared__ __align__(16) float xs[RPB * XS];    // 34816 B
    __shared__ __align__(8)  float sw2[64];         // fc2_w2 [32][2]
    __shared__ float shead[19];  // [0..7]=f1w1 [8..11]=f1b1 [12..15]=f1w2 [16]=f1b2 [17,18]=b2

    const int tid  = threadIdx.x;
    const int lane = tid & 31;
    const int wid  = tid >> 5;
    const int rowblock = blockIdx.x * RPB;

    // tiny param staging
    if (tid < 64) sw2[tid] = fc2_w2[tid];
    if (tid < 8)        shead[tid]      = fc1_w1[tid];
    else if (tid < 12)  shead[tid]      = fc1_b1[tid - 8];
    else if (tid < 16)  shead[tid]      = fc1_w2[tid - 12];
    else if (tid == 16) shead[16]       = fc1_b2[0];
    else if (tid == 17) shead[17]       = fc2_b2[0];
    else if (tid == 18) shead[18]       = fc2_b2[1];

    // ================= Phase 1: this thread scans ONE row =================
    {
        const int r = rowblock + tid;
        const float4* dp = reinterpret_cast<const float4*>(dist) + (size_t)r * 8;
        const int4*   vp = reinterpret_cast<const int4*>(vals) + (size_t)r * 8;

        float4* xv = reinterpret_cast<float4*>(xs + tid * XS);

        float4 d0 = dp[0], d1 = dp[1], d2 = dp[2], d3 = dp[3],
               d4 = dp[4], d5 = dp[5], d6 = dp[6], d7 = dp[7];
        int4   v0 = vp[0], v1 = vp[1], v2 = vp[2], v3 = vp[3],
               v4 = vp[4], v5 = vp[5], v6 = vp[6], v7 = vp[7];

        xv[0] = d0; xv[1] = d1; xv[2] = d2; xv[3] = d3;
        xv[4] = d4; xv[5] = d5; xv[6] = d6; xv[7] = d7;

        // prefix distinct-nonzero-label counts (labels in [0,100); bit0 preset)
        unsigned long long m0 = 1ull, m1 = 0ull;
        int cnt = 0;
        int4 vv4[8] = {v0, v1, v2, v3, v4, v5, v6, v7};
#pragma unroll
        for (int i = 0; i < 8; i++) {
            float t0, t1, t2, t3;
#pragma unroll
            for (int e = 0; e < 4; e++) {
                int vv = (e == 0) ? vv4[i].x : (e == 1) ? vv4[i].y
                       : (e == 2) ? vv4[i].z : vv4[i].w;
                unsigned long long bit = 1ull << (vv & 63);
                bool hi = (vv & 64) != 0;
                unsigned long long cur = hi ? m1 : m0;
                cnt += (int)((cur & bit) == 0ull);
                cur |= bit;
                if (hi) m1 = cur; else m0 = cur;
                float cf = (float)cnt;
                if (e == 0) t0 = cf; else if (e == 1) t1 = cf;
                else if (e == 2) t2 = cf; else t3 = cf;
            }
            xv[8 + i] = make_float4(t0, t1, t2, t3);
        }
    }

    // ---- per-lane weight column, packed over k pairs: 32 x 64-bit regs ----
    unsigned long long wpk[32];
#pragma unroll
    for (int m = 0; m < 32; m++)
        wpk[m] = pack2(fc2_w1[(2 * m) * 32 + lane],
                       fc2_w1[(2 * m + 1) * 32 + lane]);
    const float b1 = fc2_b1[lane];

    __syncthreads();

    // ========= Phase 2a: warp sweeps its 32 rows, 2 rows/iter, f32x2 ======
    const int wrow0 = wid * 32;
#pragma unroll 1
    for (int p = 0; p < 16; p++) {
        const int ra = wrow0 + 2 * p;
        const ulonglong2* xa = reinterpret_cast<const ulonglong2*>(xs + ra * XS);
        const ulonglong2* xb = reinterpret_cast<const ulonglong2*>(xs + (ra + 1) * XS);

        unsigned long long acca = 0ull, accb = 0ull;
#pragma unroll
        for (int c = 0; c < 16; c++) {
            ulonglong2 A = xa[c];                   // uniform broadcast LDS.128
            ulonglong2 B = xb[c];
            acca = fma2(A.x, wpk[2 * c],     acca);
            accb = fma2(B.x, wpk[2 * c],     accb);
            acca = fma2(A.y, wpk[2 * c + 1], acca);
            accb = fma2(B.y, wpk[2 * c + 1], accb);
        }
        float alo, ahi, blo, bhi;
        unpack2(acca, alo, ahi);
        unpack2(accb, blo, bhi);
        float hA = fast_tanh(alo + ahi + b1);
        float hB = fast_tanh(blo + bhi + b1);
        // overlay h into the dead x-region of the same rows
        xs[ra * XS + lane]       = hA;
        xs[(ra + 1) * XS + lane] = hB;
    }

    __syncwarp();   // h written and read by the same warp

    // ========= Phase 2b: one row per lane — no shuffles =========
    {
        const float* hrow = xs + (wrow0 + lane) * XS;
        float o0 = shead[17], o1 = shead[18];
#pragma unroll
        for (int j = 0; j < 32; j++) {
            float hj = hrow[j];
            o0 = fmaf(hj, sw2[2 * j],     o0);
            o1 = fmaf(hj, sw2[2 * j + 1], o1);
        }

        float r = shead[16];
#pragma unroll
        for (int c = 0; c < 4; c++) {
            float t = fast_tanh(fmaf(o1, shead[4 + c],
                                fmaf(o0, shead[c], shead[8 + c])));
            r = fmaf(t, shead[12 + c], r);
        }

        float* op = out + (size_t)(rowblock + wrow0 + lane) * 3;
        op[0] = o0;
        op[1] = o1;
        op[2] = r;
    }
}

extern "C" void kernel_launch(void* const* d_in, const int* in_sizes, int n_in,
                              void* d_out, int out_size)
{
    const int*   vals   = (const int*)  d_in[0];
    const float* dist   = (const float*)d_in[1];
    const float* fc2_w1 = (const float*)d_in[2];
    const float* fc2_b1 = (const float*)d_in[3];
    const float* fc2_w2 = (const float*)d_in[4];
    const float* fc2_b2 = (const float*)d_in[5];
    const float* fc1_w1 = (const float*)d_in[6];
    const float* fc1_b1 = (const float*)d_in[7];
    const float* fc1_w2 = (const float*)d_in[8];
    const float* fc1_b2 = (const float*)d_in[9];
    float* out = (float*)d_out;

    const int blocks = ROWS / RPB;   // 256
    metak_kernel<<<blocks, TPB>>>(vals, dist,
                                  fc2_w1, fc2_b1, fc2_w2, fc2_b2,
                                  fc1_w1, fc1_b1, fc1_w2, fc1_b2,
                                  out);
}